// round 9
// baseline (speedup 1.0000x reference)
#include <cuda_runtime.h>
#include <cuda_bf16.h>

// out[b,t,:] = W[onehot_index(X[b,t,:]), :] + pos[t,:]
// X: (2, 2048, 32000) fp32 one-hot -> chunked early-exit scan, fused gather.
// W: (32000, 1024) fp32, pos: (2048, 1024) fp32, out: (2, 2048, 1024) fp32

#define BATCH 2
#define CTX   2048
#define VOCAB 32000
#define EMB   1024
#define NROWS (BATCH * CTX)              // 4096
#define ROW_F4 (VOCAB / 4)               // 8000 float4 per X row
#define THREADS 256
// Chunk = 2 float4/thread = 512 float4 = 2048 floats.
#define CHUNK_F4 (THREADS * 2)           // 512
#define NCHUNKS ((ROW_F4 + CHUNK_F4 - 1) / CHUNK_F4)   // 16 (last partial)

#define X_ELEMS (BATCH * CTX * VOCAB)    // 131,072,000
#define W_ELEMS (VOCAB * EMB)            // 32,768,000
#define P_ELEMS (CTX * EMB)              // 2,097,152

__global__ void __launch_bounds__(THREADS)
embed_fused_kernel(const float4* __restrict__ X4,
                   const float4* __restrict__ W4,
                   const float4* __restrict__ P4,
                   float4* __restrict__ out4) {
    __shared__ int s_u;                       // vocab index for this row

    const int row = blockIdx.x;               // b*CTX + t
    const int t   = row & (CTX - 1);          // CTX = 2048, power of two
    const int tid = threadIdx.x;

    const float4* xrow = X4 + (long long)row * ROW_F4;

    // Prefetch pos[t] NOW — t is known, so this DRAM latency hides behind
    // the scan instead of serializing into the epilogue.
    const float4 p = P4[(long long)t * (EMB / 4) + tid];

    // ---- Phase 1: chunked early-exit scan for the single nonzero --------
    if (tid == 0) s_u = 0;                    // defensive init (one-hot => always found)
    __syncthreads();                          // order init before any finder write

    #pragma unroll 1
    for (int c = 0; c < NCHUNKS; ++c) {
        int i0 = c * CHUNK_F4 + tid;          // two strided float4 loads
        int i1 = i0 + THREADS;

        float4 v0 = (i0 < ROW_F4) ? xrow[i0] : make_float4(0.f, 0.f, 0.f, 0.f);
        float4 v1 = (i1 < ROW_F4) ? xrow[i1] : make_float4(0.f, 0.f, 0.f, 0.f);

        int found = 0;
        if (v0.x != 0.f || v0.y != 0.f || v0.z != 0.f || v0.w != 0.f) {
            int off = (v0.x != 0.f) ? 0 : (v0.y != 0.f) ? 1 : (v0.z != 0.f) ? 2 : 3;
            s_u = i0 * 4 + off;
            found = 1;
        }
        if (v1.x != 0.f || v1.y != 0.f || v1.z != 0.f || v1.w != 0.f) {
            int off = (v1.x != 0.f) ? 0 : (v1.y != 0.f) ? 1 : (v1.z != 0.f) ? 2 : 3;
            s_u = i1 * 4 + off;
            found = 1;
        }
        // Barrier + OR-reduce across the block; also publishes s_u.
        if (__syncthreads_or(found)) break;
    }

    // ---- Phase 2: gather W row, add prefetched pos -> out row -----------
    const int u = s_u;                        // broadcast LDS
    const int c = tid;                        // EMB/4 = 256 float4 per row

    float4 w = W4[(long long)u * (EMB / 4) + c];
    float4 o;
    o.x = w.x + p.x;
    o.y = w.y + p.y;
    o.z = w.z + p.z;
    o.w = w.w + p.w;
    out4[(long long)row * (EMB / 4) + c] = o;
}

extern "C" void kernel_launch(void* const* d_in, const int* in_sizes, int n_in,
                              void* d_out, int out_size) {
    // Resolve inputs BY ELEMENT COUNT (robust to metadata ordering):
    //   X: 131,072,000   W: 32,768,000   pos: 2,097,152
    const float4* X4 = nullptr;
    const float4* W4 = nullptr;
    const float4* P4 = nullptr;
    for (int i = 0; i < n_in; ++i) {
        if (in_sizes[i] == X_ELEMS)      X4 = (const float4*)d_in[i];
        else if (in_sizes[i] == W_ELEMS) W4 = (const float4*)d_in[i];
        else if (in_sizes[i] == P_ELEMS) P4 = (const float4*)d_in[i];
    }
    float4* out4 = (float4*)d_out;           // out (4,194,304 f32)

    embed_fused_kernel<<<NROWS, THREADS>>>(X4, W4, P4, out4);
}